// round 13
// baseline (speedup 1.0000x reference)
#include <cuda_runtime.h>
#include <cuda_fp16.h>
#include <cstdint>

// ============================================================================
// DivFreeNetwork via mma.sync m16n8k16 fp16 (single-pass, fp32 accum).
// R13: R12 + 3 CTAs/SM (smem 70.6KB*3 = 212KB fits; regs were never the
// limiter) + C-stride padded to 268 floats (bank-conflict-free float4).
// ============================================================================

#define THREADS 256

// smem byte offsets
#define SM_A    0                  // fp16 A image, 64 * 528
#define SM_WP   33792              // 4 pairs * 2 bufs * 4608 = 36864
#define SMEM_TOTAL 70656
#define ASTRIDE 528                // bytes per A row (264 fp16: 256 + 8 pad)
#define PSTRIDE 144                // bytes per slab k-row (72 fp16: 64 + 8 pad)
#define SLAB_BYTES 4608            // 32 k * 144
#define CSTRIDE_F 268              // floats per C row (67 float4s: odd -> no BC)

// Pre-baked weights: [chunk(32)][pair(4)][32k][72] fp16  (~0.59 MB)
__device__ __align__(16) __half g_wp[32 * 4 * 32 * 72];

// ---------------------------------------------------------------------------
__device__ __forceinline__ uint32_t smem_u32(const void* p) {
    uint32_t a;
    asm("{ .reg .u64 t; cvta.to.shared.u64 t, %1; cvt.u32.u64 %0, t; }"
        : "=r"(a) : "l"(p));
    return a;
}
__device__ __forceinline__ void cp_async16(uint32_t saddr, const void* g) {
    asm volatile("cp.async.cg.shared.global [%0], [%1], 16;"
                 :: "r"(saddr), "l"(g) : "memory");
}
__device__ __forceinline__ void cp_commit() {
    asm volatile("cp.async.commit_group;" ::: "memory");
}
__device__ __forceinline__ void cp_wait_all() {
    asm volatile("cp.async.wait_group 0;" ::: "memory");
}
__device__ __forceinline__ void bar_pair(int id) {
    asm volatile("bar.sync %0, 64;" :: "r"(id) : "memory");
}

__device__ __forceinline__ void ldsm_x4(uint32_t* r, uint32_t addr) {
    asm volatile("ldmatrix.sync.aligned.m8n8.x4.shared.b16 {%0,%1,%2,%3}, [%4];"
                 : "=r"(r[0]), "=r"(r[1]), "=r"(r[2]), "=r"(r[3]) : "r"(addr));
}
__device__ __forceinline__ void ldsm_x4t(uint32_t* r, uint32_t addr) {
    asm volatile("ldmatrix.sync.aligned.m8n8.x4.trans.shared.b16 {%0,%1,%2,%3}, [%4];"
                 : "=r"(r[0]), "=r"(r[1]), "=r"(r[2]), "=r"(r[3]) : "r"(addr));
}
__device__ __forceinline__ void mma_f16(float* d, const uint32_t* a, const uint32_t* b) {
    asm volatile(
        "mma.sync.aligned.m16n8k16.row.col.f32.f16.f16.f32 "
        "{%0,%1,%2,%3}, {%4,%5,%6,%7}, {%8,%9}, {%0,%1,%2,%3};"
        : "+f"(d[0]), "+f"(d[1]), "+f"(d[2]), "+f"(d[3])
        : "r"(a[0]), "r"(a[1]), "r"(a[2]), "r"(a[3]), "r"(b[0]), "r"(b[1]));
}

// pack two fp32 into fp16x2 (low 16 bits = first element)
__device__ __forceinline__ uint32_t packh2(float a0, float a1) {
    uint32_t r;
    asm("cvt.rn.f16x2.f32 %0, %1, %2;" : "=r"(r) : "f"(a1), "f"(a0));
    return r;
}

// ---------------------------------------------------------------------------
// Prep: convert weights to fp16, transpose to per-pair [k][n] slabs.
// ---------------------------------------------------------------------------
__global__ void prep_kernel(const float* __restrict__ w_hid,
                            const float* __restrict__ w_out) {
    int e = blockIdx.x * blockDim.x + threadIdx.x;     // 0 .. 262143
    int l = e >> 16;
    int k = (e >> 8) & 255;
    int n = e & 255;
    const float* W = (l < 3) ? (w_hid + l * 65536) : w_out;
    float v = W[k * 256 + n];
    int chunk = l * 8 + (k >> 5), kl = k & 31;
    int pair = n >> 6, nl = n & 63;
    g_wp[(((size_t)chunk * 4 + pair) * 32 + kl) * 72 + nl] = __float2half(v);
}

// ---------------------------------------------------------------------------
__global__ __launch_bounds__(THREADS, 3)
void divfree_main(const float* __restrict__ x,
                  const float* __restrict__ w_in,
                  const float* __restrict__ b_in,
                  const float* __restrict__ b_hid,
                  const float* __restrict__ b_out,
                  float* __restrict__ out)
{
    extern __shared__ char smem[];
    const uint32_t sb = smem_u32(smem);
    const int tid  = threadIdx.x;
    const int wid  = tid >> 5;
    const int lane = tid & 31;
    const int wm   = wid & 1;     // row group (32 rows of 64)
    const int pair = wid >> 1;    // col quarter (64 cols of 256)
    const int wp_tid = tid & 63;  // thread id within pair

    // ---- prefetch this pair's slab of chunk 0 into buffer 0 ----
    {
        const char* src = (const char*)g_wp + (size_t)pair * SLAB_BYTES;
        const uint32_t dst = sb + SM_WP + (uint32_t)(pair * 2) * SLAB_BYTES;
        for (int i = wp_tid; i < SLAB_BYTES / 16; i += 64)
            cp_async16(dst + (uint32_t)i * 16, src + (size_t)i * 16);
        cp_commit();
    }

    // ---- layer 0: z(3) -> 256, identity tangent seeds, silu ----
    for (int idx = tid; idx < 64 * 128; idx += THREADS) {
        int row = idx >> 7;
        int cp  = idx & 127;
        int c0  = cp * 2;
        int rt  = row & 3;
        int samp = blockIdx.x * 16 + (row >> 2);
        float z0 = __ldg(x + samp * 3 + 0);
        float z1 = __ldg(x + samp * 3 + 1);
        float z2 = __ldg(x + samp * 3 + 2);
        float a[2];
#pragma unroll
        for (int q = 0; q < 2; q++) {
            int c = c0 + q;
            float w0 = __ldg(w_in + c);
            float w1 = __ldg(w_in + 256 + c);
            float w2 = __ldg(w_in + 512 + c);
            float pre = __ldg(b_in + c) + z0 * w0 + z1 * w1 + z2 * w2;
            float sig = 1.f / (1.f + __expf(-pre));
            if (rt == 0) a[q] = pre * sig;
            else {
                float ds = sig * (1.f + pre * (1.f - sig));
                a[q] = ds * (rt == 1 ? w0 : (rt == 2 ? w1 : w2));
            }
        }
        *(uint32_t*)(smem + SM_A + row * ASTRIDE + c0 * 2) = packh2(a[0], a[1]);
    }
    __syncthreads();                   // layer-0 A visible to all pairs

    // ldmatrix base addresses (A: 32 rows per warp -> 2 m16 tiles)
    uint32_t aBase[2];
#pragma unroll
    for (int mt = 0; mt < 2; mt++) {
        int row = wm * 32 + mt * 16 + (lane & 15);
        aBase[mt] = sb + SM_A + (uint32_t)row * ASTRIDE + 16u * (lane >> 4);
    }
    // B (per-pair slab): addr = slab + (lane&15)*PSTRIDE + 16*(lane>>4)
    //                         + k16*16*PSTRIDE + nt*32
    const uint32_t bOff = (uint32_t)(lane & 15) * PSTRIDE + 16u * (lane >> 4);

    const uint32_t vsrc  = (lane & 0x10) | (lane & 3);   // value-row lane in quad
    const bool     isval = (lane & 0xC) == 0;

    int c = 0;
    for (int L = 0; L < 4; L++) {
        float acc[2][8][4];
#pragma unroll
        for (int mt = 0; mt < 2; mt++)
#pragma unroll
            for (int nt = 0; nt < 8; nt++)
#pragma unroll
                for (int j = 0; j < 4; j++) acc[mt][nt][j] = 0.f;

        for (int kc = 0; kc < 8; kc++, c++) {
            // A fragments are layer-stable: load before the wait so LDS
            // latency overlaps the B-slab arrival + barrier.
            const uint32_t k0b = (uint32_t)kc * 64;      // 32 k = 64 bytes
            uint32_t a[2][2][4];                          // [k16][mt][4]
            ldsm_x4(a[0][0], aBase[0] + k0b);
            ldsm_x4(a[0][1], aBase[1] + k0b);
            ldsm_x4(a[1][0], aBase[0] + k0b + 32);
            ldsm_x4(a[1][1], aBase[1] + k0b + 32);

            cp_wait_all();
            bar_pair(pair + 1);           // pair's slab ready, prior reads done

            if (c + 1 < 32) {             // prefetch this pair's next slab
                const char* src = (const char*)g_wp
                    + ((size_t)(c + 1) * 4 + pair) * SLAB_BYTES;
                const uint32_t dst = sb + SM_WP
                    + (uint32_t)(pair * 2 + ((c + 1) & 1)) * SLAB_BYTES;
                for (int i = wp_tid; i < SLAB_BYTES / 16; i += 64)
                    cp_async16(dst + (uint32_t)i * 16, src + (size_t)i * 16);
                cp_commit();
            }

            const uint32_t bk = sb + SM_WP
                + (uint32_t)(pair * 2 + (c & 1)) * SLAB_BYTES + bOff;
#pragma unroll
            for (int k16 = 0; k16 < 2; k16++) {
                uint32_t b[4][4];
                const uint32_t bka = bk + (uint32_t)k16 * (16 * PSTRIDE);
                ldsm_x4t(b[0], bka);
                ldsm_x4t(b[1], bka + 32);
                ldsm_x4t(b[2], bka + 64);
                ldsm_x4t(b[3], bka + 96);
#pragma unroll
                for (int q = 0; q < 4; q++) {
#pragma unroll
                    for (int mt = 0; mt < 2; mt++) {
                        mma_f16(acc[mt][q * 2],     a[k16][mt], b[q]);
                        mma_f16(acc[mt][q * 2 + 1], a[k16][mt], b[q] + 2);
                    }
                }
            }
        }
        __syncthreads();   // all pairs done reading this layer's A

        if (L < 3) {
            // ---- mid-layer epilogue: silu + tangent scaling -> A fp16 ----
            const float* bias = b_hid + L * 256;
#pragma unroll
            for (int mt = 0; mt < 2; mt++) {
                int rlo = wm * 32 + mt * 16 + (lane >> 2);
#pragma unroll
                for (int nt8 = 0; nt8 < 8; nt8++) {
                    int cc = pair * 64 + nt8 * 8 + (lane & 3) * 2;
                    float2 bv = *(const float2*)(bias + cc);
                    float* a4 = acc[mt][nt8];
                    float s0 = __shfl_sync(0xffffffffu, a4[0], vsrc);
                    float s1 = __shfl_sync(0xffffffffu, a4[1], vsrc);
                    float s2 = __shfl_sync(0xffffffffu, a4[2], vsrc);
                    float s3 = __shfl_sync(0xffffffffu, a4[3], vsrc);
                    float o[4];
                    const float bb[4] = {bv.x, bv.y, bv.x, bv.y};
                    const float ss[4] = {s0, s1, s2, s3};
#pragma unroll
                    for (int j = 0; j < 4; j++) {
                        float pre = ss[j] + bb[j];
                        float sig = 1.f / (1.f + __expf(-pre));
                        if (isval) o[j] = pre * sig;
                        else {
                            float ds = sig * (1.f + pre * (1.f - sig));
                            o[j] = ds * a4[j];
                        }
                    }
                    *(uint32_t*)(smem + SM_A + rlo * ASTRIDE + cc * 2)
                        = packh2(o[0], o[1]);
                    *(uint32_t*)(smem + SM_A + (rlo + 8) * ASTRIDE + cc * 2)
                        = packh2(o[2], o[3]);
                }
            }
            __syncthreads();
        } else {
            // ---- final layer: dump fp32 C to smem (aliases A+slab region) ----
            float* C = (float*)smem;
#pragma unroll
            for (int mt = 0; mt < 2; mt++) {
                int rlo = wm * 32 + mt * 16 + (lane >> 2);
#pragma unroll
                for (int nt8 = 0; nt8 < 8; nt8++) {
                    int cc = pair * 64 + nt8 * 8 + (lane & 3) * 2;
                    float* a4 = acc[mt][nt8];
                    *(float2*)(C + rlo * CSTRIDE_F + cc)       = make_float2(a4[0], a4[1]);
                    *(float2*)(C + (rlo + 8) * CSTRIDE_F + cc) = make_float2(a4[2], a4[3]);
                }
            }
            __syncthreads();
        }
    }

    // ---- final epilogue: softmax mixture + JVP combine (warps 0-1) ----
    if (wid < 2) {
        const float* C = (const float*)smem;
        const int row  = wid * 32 + lane;
        const int rt   = lane & 3;
        const int base = lane & ~3;
        const float* Crow = C + row * CSTRIDE_F;

        float E = 0.f, P0 = 0.f, P1 = 0.f, P2 = 0.f;
        float Q = 0.f, R0 = 0.f, R1 = 0.f, R2 = 0.f;
        float Mx = -1e30f;
        for (int cb = 0; cb < 8; cb++) {
            float4 q4[8];
#pragma unroll
            for (int m = 0; m < 8; m++)
                q4[m] = *(const float4*)(Crow + cb * 32 + m * 4);
            float lg[8];
            float cmax = -1e30f;
#pragma unroll
            for (int m = 0; m < 8; m++) {
                lg[m] = __shfl_sync(0xffffffffu, q4[m].x, base)
                        + __ldg(b_out + cb * 32 + m * 4);
                cmax = fmaxf(cmax, lg[m]);
            }
            float nM = fmaxf(Mx, cmax);
            float sc = __expf(Mx - nM);
            E *= sc; P0 *= sc; P1 *= sc; P2 *= sc;
            Q *= sc; R0 *= sc; R1 *= sc; R2 *= sc;
            Mx = nM;
#pragma unroll
            for (int m = 0; m < 8; m++) {
                float e = __expf(lg[m] - Mx);
                int c0 = cb * 32 + m * 4;
                float4 bo = *(const float4*)(b_out + c0);
                float v0 = __shfl_sync(0xffffffffu, q4[m].y, base) + bo.y;
                float v1 = __shfl_sync(0xffffffffu, q4[m].z, base) + bo.z;
                float v2 = __shfl_sync(0xffffffffu, q4[m].w, base) + bo.w;
                if (rt == 0) {
                    E += e; P0 += e * v0; P1 += e * v1; P2 += e * v2;
                } else {
                    float gl = q4[m].x;
                    Q  += e * gl;
                    R0 += e * (gl * v0 + q4[m].y);
                    R1 += e * (gl * v1 + q4[m].z);
                    R2 += e * (gl * v2 + q4[m].w);
                }
            }
        }
        float Ev = __shfl_sync(0xffffffffu, E, base);
        float p0 = __shfl_sync(0xffffffffu, P0, base);
        float p1 = __shfl_sync(0xffffffffu, P1, base);
        float p2 = __shfl_sync(0xffffffffu, P2, base);
        float inv = 1.f / Ev;
        float t0 = p0 * inv, t1 = p1 * inv, t2 = p2 * inv;
        float S  = Q * inv;
        float dt0 = R0 * inv - S * t0;
        float dt1 = R1 * inv - S * t1;
        float dt2 = R2 * inv - S * t2;
        // dtri[t][k] lives on lane base+1+k as dt{t}
        float d01 = __shfl_sync(0xffffffffu, dt0, base + 2);
        float d12 = __shfl_sync(0xffffffffu, dt1, base + 3);
        float d00 = __shfl_sync(0xffffffffu, dt0, base + 1);
        float d22 = __shfl_sync(0xffffffffu, dt2, base + 3);
        float d10 = __shfl_sync(0xffffffffu, dt1, base + 1);
        float d21 = __shfl_sync(0xffffffffu, dt2, base + 2);
        if (rt == 0) {
            int samp = blockIdx.x * 16 + (row >> 2);
            out[samp * 3 + 0] =  d01 + d12;
            out[samp * 3 + 1] = -d00 + d22;
            out[samp * 3 + 2] = -d10 - d21;
        }
    }
}

// ---------------------------------------------------------------------------
extern "C" void kernel_launch(void* const* d_in, const int* in_sizes, int n_in,
                              void* d_out, int out_size)
{
    const float* x     = (const float*)d_in[0];
    const float* w_in  = (const float*)d_in[1];
    const float* b_in  = (const float*)d_in[2];
    const float* w_hid = (const float*)d_in[3];
    const float* b_hid = (const float*)d_in[4];
    const float* w_out = (const float*)d_in[5];
    const float* b_out = (const float*)d_in[6];
    float*       out   = (float*)d_out;

    const int N = in_sizes[0] / 3;   // 65536 samples

    prep_kernel<<<1024, 256>>>(w_hid, w_out);

    cudaFuncSetAttribute(divfree_main,
                         cudaFuncAttributeMaxDynamicSharedMemorySize, SMEM_TOTAL);
    divfree_main<<<N / 16, THREADS, SMEM_TOTAL>>>(x, w_in, b_in, b_hid, b_out, out);
    (void)n_in; (void)out_size;
}

// round 14
// speedup vs baseline: 1.6297x; 1.6297x over previous
#include <cuda_runtime.h>
#include <cuda_fp16.h>
#include <cstdint>

// ============================================================================
// DivFreeNetwork via mma.sync m16n8k16 fp16 (single-pass, fp32 accum).
// R14: R12 base (2 CTAs/SM, 128 regs — R13's 3-CTA reg-squeeze reverted)
// + 64-k chunks (16 sync events instead of 32) + C stride 268 (no bank
// conflicts in the final-epilogue float4 reads).
// ============================================================================

#define THREADS 256

// smem byte offsets
#define SM_A    0                  // fp16 A image, 64 * 528
#define SM_WP   33792              // 4 pairs * 2 bufs * 9216 = 73728
#define SMEM_TOTAL 107520
#define ASTRIDE 528                // bytes per A row (264 fp16: 256 + 8 pad)
#define PSTRIDE 144                // bytes per slab k-row (72 fp16: 64 + 8 pad)
#define SLAB_BYTES 9216            // 64 k * 144
#define CSTRIDE_F 268              // floats per C row (odd float4 count -> no BC)

// Pre-baked weights: [chunk(16)][pair(4)][64k][72] fp16  (~0.59 MB)
__device__ __align__(16) __half g_wp[16 * 4 * 64 * 72];

// ---------------------------------------------------------------------------
__device__ __forceinline__ uint32_t smem_u32(const void* p) {
    uint32_t a;
    asm("{ .reg .u64 t; cvta.to.shared.u64 t, %1; cvt.u32.u64 %0, t; }"
        : "=r"(a) : "l"(p));
    return a;
}
__device__ __forceinline__ void cp_async16(uint32_t saddr, const void* g) {
    asm volatile("cp.async.cg.shared.global [%0], [%1], 16;"
                 :: "r"(saddr), "l"(g) : "memory");
}
__device__ __forceinline__ void cp_commit() {
    asm volatile("cp.async.commit_group;" ::: "memory");
}
__device__ __forceinline__ void cp_wait_all() {
    asm volatile("cp.async.wait_group 0;" ::: "memory");
}
__device__ __forceinline__ void bar_pair(int id) {
    asm volatile("bar.sync %0, 64;" :: "r"(id) : "memory");
}

__device__ __forceinline__ void ldsm_x4(uint32_t* r, uint32_t addr) {
    asm volatile("ldmatrix.sync.aligned.m8n8.x4.shared.b16 {%0,%1,%2,%3}, [%4];"
                 : "=r"(r[0]), "=r"(r[1]), "=r"(r[2]), "=r"(r[3]) : "r"(addr));
}
__device__ __forceinline__ void ldsm_x4t(uint32_t* r, uint32_t addr) {
    asm volatile("ldmatrix.sync.aligned.m8n8.x4.trans.shared.b16 {%0,%1,%2,%3}, [%4];"
                 : "=r"(r[0]), "=r"(r[1]), "=r"(r[2]), "=r"(r[3]) : "r"(addr));
}
__device__ __forceinline__ void mma_f16(float* d, const uint32_t* a, const uint32_t* b) {
    asm volatile(
        "mma.sync.aligned.m16n8k16.row.col.f32.f16.f16.f32 "
        "{%0,%1,%2,%3}, {%4,%5,%6,%7}, {%8,%9}, {%0,%1,%2,%3};"
        : "+f"(d[0]), "+f"(d[1]), "+f"(d[2]), "+f"(d[3])
        : "r"(a[0]), "r"(a[1]), "r"(a[2]), "r"(a[3]), "r"(b[0]), "r"(b[1]));
}

// pack two fp32 into fp16x2 (low 16 bits = first element)
__device__ __forceinline__ uint32_t packh2(float a0, float a1) {
    uint32_t r;
    asm("cvt.rn.f16x2.f32 %0, %1, %2;" : "=r"(r) : "f"(a1), "f"(a0));
    return r;
}

// ---------------------------------------------------------------------------
// Prep: convert weights to fp16, transpose to per-pair [k][n] slabs.
// ---------------------------------------------------------------------------
__global__ void prep_kernel(const float* __restrict__ w_hid,
                            const float* __restrict__ w_out) {
    int e = blockIdx.x * blockDim.x + threadIdx.x;     // 0 .. 262143
    int l = e >> 16;
    int k = (e >> 8) & 255;
    int n = e & 255;
    const float* W = (l < 3) ? (w_hid + l * 65536) : w_out;
    float v = W[k * 256 + n];
    int chunk = l * 4 + (k >> 6), kl = k & 63;
    int pair = n >> 6, nl = n & 63;
    g_wp[(((size_t)chunk * 4 + pair) * 64 + kl) * 72 + nl] = __float2half(v);
}

// ---------------------------------------------------------------------------
__global__ __launch_bounds__(THREADS, 2)
void divfree_main(const float* __restrict__ x,
                  const float* __restrict__ w_in,
                  const float* __restrict__ b_in,
                  const float* __restrict__ b_hid,
                  const float* __restrict__ b_out,
                  float* __restrict__ out)
{
    extern __shared__ char smem[];
    const uint32_t sb = smem_u32(smem);
    const int tid  = threadIdx.x;
    const int wid  = tid >> 5;
    const int lane = tid & 31;
    const int wm   = wid & 1;     // row group (32 rows of 64)
    const int pair = wid >> 1;    // col quarter (64 cols of 256)
    const int wp_tid = tid & 63;  // thread id within pair

    // ---- prefetch this pair's slab of chunk 0 into buffer 0 ----
    {
        const char* src = (const char*)g_wp + (size_t)pair * SLAB_BYTES;
        const uint32_t dst = sb + SM_WP + (uint32_t)(pair * 2) * SLAB_BYTES;
        for (int i = wp_tid; i < SLAB_BYTES / 16; i += 64)
            cp_async16(dst + (uint32_t)i * 16, src + (size_t)i * 16);
        cp_commit();
    }

    // ---- layer 0: z(3) -> 256, identity tangent seeds, silu ----
    for (int idx = tid; idx < 64 * 128; idx += THREADS) {
        int row = idx >> 7;
        int cp  = idx & 127;
        int c0  = cp * 2;
        int rt  = row & 3;
        int samp = blockIdx.x * 16 + (row >> 2);
        float z0 = __ldg(x + samp * 3 + 0);
        float z1 = __ldg(x + samp * 3 + 1);
        float z2 = __ldg(x + samp * 3 + 2);
        float a[2];
#pragma unroll
        for (int q = 0; q < 2; q++) {
            int c = c0 + q;
            float w0 = __ldg(w_in + c);
            float w1 = __ldg(w_in + 256 + c);
            float w2 = __ldg(w_in + 512 + c);
            float pre = __ldg(b_in + c) + z0 * w0 + z1 * w1 + z2 * w2;
            float sig = 1.f / (1.f + __expf(-pre));
            if (rt == 0) a[q] = pre * sig;
            else {
                float ds = sig * (1.f + pre * (1.f - sig));
                a[q] = ds * (rt == 1 ? w0 : (rt == 2 ? w1 : w2));
            }
        }
        *(uint32_t*)(smem + SM_A + row * ASTRIDE + c0 * 2) = packh2(a[0], a[1]);
    }
    __syncthreads();                   // layer-0 A visible to all pairs

    // ldmatrix base addresses (A: 32 rows per warp -> 2 m16 tiles)
    uint32_t aBase[2];
#pragma unroll
    for (int mt = 0; mt < 2; mt++) {
        int row = wm * 32 + mt * 16 + (lane & 15);
        aBase[mt] = sb + SM_A + (uint32_t)row * ASTRIDE + 16u * (lane >> 4);
    }
    // B (per-pair slab): addr = slab + (lane&15)*PSTRIDE + 16*(lane>>4)
    const uint32_t bOff = (uint32_t)(lane & 15) * PSTRIDE + 16u * (lane >> 4);

    const uint32_t vsrc  = (lane & 0x10) | (lane & 3);   // value-row lane in quad
    const bool     isval = (lane & 0xC) == 0;

    int c = 0;
    for (int L = 0; L < 4; L++) {
        float acc[2][8][4];
#pragma unroll
        for (int mt = 0; mt < 2; mt++)
#pragma unroll
            for (int nt = 0; nt < 8; nt++)
#pragma unroll
                for (int j = 0; j < 4; j++) acc[mt][nt][j] = 0.f;

        for (int kc = 0; kc < 4; kc++, c++) {       // 64-k chunks
            // first sub-chunk's A fragments: load BEFORE the wait so LDS
            // latency overlaps the B-slab arrival + barrier.
            const uint32_t k0b = (uint32_t)kc * 128;     // 64 k = 128 bytes
            uint32_t a[2][2][4];                          // [k16][mt][4]
            ldsm_x4(a[0][0], aBase[0] + k0b);
            ldsm_x4(a[0][1], aBase[1] + k0b);
            ldsm_x4(a[1][0], aBase[0] + k0b + 32);
            ldsm_x4(a[1][1], aBase[1] + k0b + 32);

            cp_wait_all();
            bar_pair(pair + 1);           // pair's slab ready, prior reads done

            if (c + 1 < 16) {             // prefetch this pair's next slab
                const char* src = (const char*)g_wp
                    + ((size_t)(c + 1) * 4 + pair) * SLAB_BYTES;
                const uint32_t dst = sb + SM_WP
                    + (uint32_t)(pair * 2 + ((c + 1) & 1)) * SLAB_BYTES;
                for (int i = wp_tid; i < SLAB_BYTES / 16; i += 64)
                    cp_async16(dst + (uint32_t)i * 16, src + (size_t)i * 16);
                cp_commit();
            }

            const uint32_t bk = sb + SM_WP
                + (uint32_t)(pair * 2 + (c & 1)) * SLAB_BYTES + bOff;

#pragma unroll
            for (int ks2 = 0; ks2 < 2; ks2++) {     // two 32-k sub-chunks
                if (ks2 == 1) {                      // second sub-chunk A
                    ldsm_x4(a[0][0], aBase[0] + k0b + 64);
                    ldsm_x4(a[0][1], aBase[1] + k0b + 64);
                    ldsm_x4(a[1][0], aBase[0] + k0b + 96);
                    ldsm_x4(a[1][1], aBase[1] + k0b + 96);
                }
#pragma unroll
                for (int k16 = 0; k16 < 2; k16++) {
                    uint32_t b[4][4];
                    const uint32_t bka = bk
                        + (uint32_t)(ks2 * 2 + k16) * (16 * PSTRIDE);
                    ldsm_x4t(b[0], bka);
                    ldsm_x4t(b[1], bka + 32);
                    ldsm_x4t(b[2], bka + 64);
                    ldsm_x4t(b[3], bka + 96);
#pragma unroll
                    for (int q = 0; q < 4; q++) {
#pragma unroll
                        for (int mt = 0; mt < 2; mt++) {
                            mma_f16(acc[mt][q * 2],     a[k16][mt], b[q]);
                            mma_f16(acc[mt][q * 2 + 1], a[k16][mt], b[q] + 2);
                        }
                    }
                }
            }
        }
        __syncthreads();   // all pairs done reading this layer's A

        if (L < 3) {
            // ---- mid-layer epilogue: silu + tangent scaling -> A fp16 ----
            const float* bias = b_hid + L * 256;
#pragma unroll
            for (int mt = 0; mt < 2; mt++) {
                int rlo = wm * 32 + mt * 16 + (lane >> 2);
#pragma unroll
                for (int nt8 = 0; nt8 < 8; nt8++) {
                    int cc = pair * 64 + nt8 * 8 + (lane & 3) * 2;
                    float2 bv = *(const float2*)(bias + cc);
                    float* a4 = acc[mt][nt8];
                    float s0 = __shfl_sync(0xffffffffu, a4[0], vsrc);
                    float s1 = __shfl_sync(0xffffffffu, a4[1], vsrc);
                    float s2 = __shfl_sync(0xffffffffu, a4[2], vsrc);
                    float s3 = __shfl_sync(0xffffffffu, a4[3], vsrc);
                    float o[4];
                    const float bb[4] = {bv.x, bv.y, bv.x, bv.y};
                    const float ss[4] = {s0, s1, s2, s3};
#pragma unroll
                    for (int j = 0; j < 4; j++) {
                        float pre = ss[j] + bb[j];
                        float sig = 1.f / (1.f + __expf(-pre));
                        if (isval) o[j] = pre * sig;
                        else {
                            float ds = sig * (1.f + pre * (1.f - sig));
                            o[j] = ds * a4[j];
                        }
                    }
                    *(uint32_t*)(smem + SM_A + rlo * ASTRIDE + cc * 2)
                        = packh2(o[0], o[1]);
                    *(uint32_t*)(smem + SM_A + (rlo + 8) * ASTRIDE + cc * 2)
                        = packh2(o[2], o[3]);
                }
            }
            __syncthreads();
        } else {
            // ---- final layer: dump fp32 C to smem (aliases A+slab region) ----
            float* C = (float*)smem;
#pragma unroll
            for (int mt = 0; mt < 2; mt++) {
                int rlo = wm * 32 + mt * 16 + (lane >> 2);
#pragma unroll
                for (int nt8 = 0; nt8 < 8; nt8++) {
                    int cc = pair * 64 + nt8 * 8 + (lane & 3) * 2;
                    float* a4 = acc[mt][nt8];
                    *(float2*)(C + rlo * CSTRIDE_F + cc)       = make_float2(a4[0], a4[1]);
                    *(float2*)(C + (rlo + 8) * CSTRIDE_F + cc) = make_float2(a4[2], a4[3]);
                }
            }
            __syncthreads();
        }
    }

    // ---- final epilogue: softmax mixture + JVP combine (warps 0-1) ----
    if (wid < 2) {
        const float* C = (const float*)smem;
        const int row  = wid * 32 + lane;
        const int rt   = lane & 3;
        const int base = lane & ~3;
        const float* Crow = C + row * CSTRIDE_F;

        float E = 0.f, P0 = 0.f, P1 = 0.f, P2 = 0.f;
        float Q = 0.f, R0 = 0.f, R1 = 0.f, R2 = 0.f;
        float Mx = -1e30f;
        for (int cb = 0; cb < 8; cb++) {
            float4 q4[8];
#pragma unroll
            for (int m = 0; m < 8; m++)
                q4[m] = *(const float4*)(Crow + cb * 32 + m * 4);
            float lg[8];
            float cmax = -1e30f;
#pragma unroll
            for (int m = 0; m < 8; m++) {
                lg[m] = __shfl_sync(0xffffffffu, q4[m].x, base)
                        + __ldg(b_out + cb * 32 + m * 4);
                cmax = fmaxf(cmax, lg[m]);
            }
            float nM = fmaxf(Mx, cmax);
            float sc = __expf(Mx - nM);
            E *= sc; P0 *= sc; P1 *= sc; P2 *= sc;
            Q *= sc; R0 *= sc; R1 *= sc; R2 *= sc;
            Mx = nM;
#pragma unroll
            for (int m = 0; m < 8; m++) {
                float e = __expf(lg[m] - Mx);
                int c0 = cb * 32 + m * 4;
                float4 bo = *(const float4*)(b_out + c0);
                float v0 = __shfl_sync(0xffffffffu, q4[m].y, base) + bo.y;
                float v1 = __shfl_sync(0xffffffffu, q4[m].z, base) + bo.z;
                float v2 = __shfl_sync(0xffffffffu, q4[m].w, base) + bo.w;
                if (rt == 0) {
                    E += e; P0 += e * v0; P1 += e * v1; P2 += e * v2;
                } else {
                    float gl = q4[m].x;
                    Q  += e * gl;
                    R0 += e * (gl * v0 + q4[m].y);
                    R1 += e * (gl * v1 + q4[m].z);
                    R2 += e * (gl * v2 + q4[m].w);
                }
            }
        }
        float Ev = __shfl_sync(0xffffffffu, E, base);
        float p0 = __shfl_sync(0xffffffffu, P0, base);
        float p1 = __shfl_sync(0xffffffffu, P1, base);
        float p2 = __shfl_sync(0xffffffffu, P2, base);
        float inv = 1.f / Ev;
        float t0 = p0 * inv, t1 = p1 * inv, t2 = p2 * inv;
        float S  = Q * inv;
        float dt0 = R0 * inv - S * t0;
        float dt1 = R1 * inv - S * t1;
        float dt2 = R2 * inv - S * t2;
        // dtri[t][k] lives on lane base+1+k as dt{t}
        float d01 = __shfl_sync(0xffffffffu, dt0, base + 2);
        float d12 = __shfl_sync(0xffffffffu, dt1, base + 3);
        float d00 = __shfl_sync(0xffffffffu, dt0, base + 1);
        float d22 = __shfl_sync(0xffffffffu, dt2, base + 3);
        float d10 = __shfl_sync(0xffffffffu, dt1, base + 1);
        float d21 = __shfl_sync(0xffffffffu, dt2, base + 2);
        if (rt == 0) {
            int samp = blockIdx.x * 16 + (row >> 2);
            out[samp * 3 + 0] =  d01 + d12;
            out[samp * 3 + 1] = -d00 + d22;
            out[samp * 3 + 2] = -d10 - d21;
        }
    }
}

// ---------------------------------------------------------------------------
extern "C" void kernel_launch(void* const* d_in, const int* in_sizes, int n_in,
                              void* d_out, int out_size)
{
    const float* x     = (const float*)d_in[0];
    const float* w_in  = (const float*)d_in[1];
    const float* b_in  = (const float*)d_in[2];
    const float* w_hid = (const float*)d_in[3];
    const float* b_hid = (const float*)d_in[4];
    const float* w_out = (const float*)d_in[5];
    const float* b_out = (const float*)d_in[6];
    float*       out   = (float*)d_out;

    const int N = in_sizes[0] / 3;   // 65536 samples

    prep_kernel<<<1024, 256>>>(w_hid, w_out);

    cudaFuncSetAttribute(divfree_main,
                         cudaFuncAttributeMaxDynamicSharedMemorySize, SMEM_TOTAL);
    divfree_main<<<N / 16, THREADS, SMEM_TOTAL>>>(x, w_in, b_in, b_hid, b_out, out);
    (void)n_in; (void)out_size;
}

// round 16
// speedup vs baseline: 1.9267x; 1.1822x over previous
#include <cuda_runtime.h>
#include <cuda_fp16.h>
#include <cstdint>

// ============================================================================
// DivFreeNetwork via mma.sync m16n8k16 fp16 (single-pass, fp32 accum).
// R15: R14 base + sample-major layer-0 (4x fewer exp/LDG) + final epilogue
// parallelized across all 8 warps (per-lane softmax-state partials merged
// through smem).
// ============================================================================

#define THREADS 256

// smem byte offsets
#define SM_A    0                  // fp16 A image, 64 * 528
#define SM_WP   33792              // 4 pairs * 2 bufs * 9216 = 73728
#define SMEM_TOTAL 107520
#define ASTRIDE 528                // bytes per A row (264 fp16: 256 + 8 pad)
#define PSTRIDE 144                // bytes per slab k-row (72 fp16: 64 + 8 pad)
#define SLAB_BYTES 9216            // 64 k * 144
#define CSTRIDE_F 268              // floats per C row (odd float4 count -> no BC)
#define SM_PART 68608              // partial softmax states: 4*64*5 floats

// Pre-baked weights: [chunk(16)][pair(4)][64k][72] fp16  (~0.59 MB)
__device__ __align__(16) __half g_wp[16 * 4 * 64 * 72];

// ---------------------------------------------------------------------------
__device__ __forceinline__ uint32_t smem_u32(const void* p) {
    uint32_t a;
    asm("{ .reg .u64 t; cvta.to.shared.u64 t, %1; cvt.u32.u64 %0, t; }"
        : "=r"(a) : "l"(p));
    return a;
}
__device__ __forceinline__ void cp_async16(uint32_t saddr, const void* g) {
    asm volatile("cp.async.cg.shared.global [%0], [%1], 16;"
                 :: "r"(saddr), "l"(g) : "memory");
}
__device__ __forceinline__ void cp_commit() {
    asm volatile("cp.async.commit_group;" ::: "memory");
}
__device__ __forceinline__ void cp_wait_all() {
    asm volatile("cp.async.wait_group 0;" ::: "memory");
}
__device__ __forceinline__ void bar_pair(int id) {
    asm volatile("bar.sync %0, 64;" :: "r"(id) : "memory");
}

__device__ __forceinline__ void ldsm_x4(uint32_t* r, uint32_t addr) {
    asm volatile("ldmatrix.sync.aligned.m8n8.x4.shared.b16 {%0,%1,%2,%3}, [%4];"
                 : "=r"(r[0]), "=r"(r[1]), "=r"(r[2]), "=r"(r[3]) : "r"(addr));
}
__device__ __forceinline__ void ldsm_x4t(uint32_t* r, uint32_t addr) {
    asm volatile("ldmatrix.sync.aligned.m8n8.x4.trans.shared.b16 {%0,%1,%2,%3}, [%4];"
                 : "=r"(r[0]), "=r"(r[1]), "=r"(r[2]), "=r"(r[3]) : "r"(addr));
}
__device__ __forceinline__ void mma_f16(float* d, const uint32_t* a, const uint32_t* b) {
    asm volatile(
        "mma.sync.aligned.m16n8k16.row.col.f32.f16.f16.f32 "
        "{%0,%1,%2,%3}, {%4,%5,%6,%7}, {%8,%9}, {%0,%1,%2,%3};"
        : "+f"(d[0]), "+f"(d[1]), "+f"(d[2]), "+f"(d[3])
        : "r"(a[0]), "r"(a[1]), "r"(a[2]), "r"(a[3]), "r"(b[0]), "r"(b[1]));
}

// pack two fp32 into fp16x2 (low 16 bits = first element)
__device__ __forceinline__ uint32_t packh2(float a0, float a1) {
    uint32_t r;
    asm("cvt.rn.f16x2.f32 %0, %1, %2;" : "=r"(r) : "f"(a1), "f"(a0));
    return r;
}

// ---------------------------------------------------------------------------
// Prep: convert weights to fp16, transpose to per-pair [k][n] slabs.
// ---------------------------------------------------------------------------
__global__ void prep_kernel(const float* __restrict__ w_hid,
                            const float* __restrict__ w_out) {
    int e = blockIdx.x * blockDim.x + threadIdx.x;     // 0 .. 262143
    int l = e >> 16;
    int k = (e >> 8) & 255;
    int n = e & 255;
    const float* W = (l < 3) ? (w_hid + l * 65536) : w_out;
    float v = W[k * 256 + n];
    int chunk = l * 4 + (k >> 6), kl = k & 63;
    int pair = n >> 6, nl = n & 63;
    g_wp[(((size_t)chunk * 4 + pair) * 64 + kl) * 72 + nl] = __float2half(v);
}

// ---------------------------------------------------------------------------
__global__ __launch_bounds__(THREADS, 2)
void divfree_main(const float* __restrict__ x,
                  const float* __restrict__ w_in,
                  const float* __restrict__ b_in,
                  const float* __restrict__ b_hid,
                  const float* __restrict__ b_out,
                  float* __restrict__ out)
{
    extern __shared__ char smem[];
    const uint32_t sb = smem_u32(smem);
    const int tid  = threadIdx.x;
    const int wid  = tid >> 5;
    const int lane = tid & 31;
    const int wm   = wid & 1;     // row group (32 rows of 64)
    const int pair = wid >> 1;    // col quarter (64 cols of 256)
    const int wp_tid = tid & 63;  // thread id within pair

    // ---- prefetch this pair's slab of chunk 0 into buffer 0 ----
    {
        const char* src = (const char*)g_wp + (size_t)pair * SLAB_BYTES;
        const uint32_t dst = sb + SM_WP + (uint32_t)(pair * 2) * SLAB_BYTES;
        for (int i = wp_tid; i < SLAB_BYTES / 16; i += 64)
            cp_async16(dst + (uint32_t)i * 16, src + (size_t)i * 16);
        cp_commit();
    }

    // ---- layer 0 (sample-major): z(3) -> 256, silu + identity-seed JVP.
    // One (sample, colpair) item computes pre/sig/ds ONCE and emits all 4 rows.
    for (int it = tid; it < 16 * 128; it += THREADS) {
        int sl = it >> 7;            // local sample 0..15
        int cp = it & 127;
        int c0 = cp * 2;
        int samp = blockIdx.x * 16 + sl;
        float z0 = __ldg(x + samp * 3 + 0);
        float z1 = __ldg(x + samp * 3 + 1);
        float z2 = __ldg(x + samp * 3 + 2);
        float w00 = __ldg(w_in + c0),       w01 = __ldg(w_in + c0 + 1);
        float w10 = __ldg(w_in + 256 + c0), w11 = __ldg(w_in + 256 + c0 + 1);
        float w20 = __ldg(w_in + 512 + c0), w21 = __ldg(w_in + 512 + c0 + 1);
        float pre0 = __ldg(b_in + c0)     + z0 * w00 + z1 * w10 + z2 * w20;
        float pre1 = __ldg(b_in + c0 + 1) + z0 * w01 + z1 * w11 + z2 * w21;
        float sig0 = 1.f / (1.f + __expf(-pre0));
        float sig1 = 1.f / (1.f + __expf(-pre1));
        float ds0 = sig0 * (1.f + pre0 * (1.f - sig0));
        float ds1 = sig1 * (1.f + pre1 * (1.f - sig1));
        char* rowp = smem + SM_A + (sl * 4) * ASTRIDE + c0 * 2;
        *(uint32_t*)(rowp)               = packh2(pre0 * sig0, pre1 * sig1);
        *(uint32_t*)(rowp + ASTRIDE)     = packh2(ds0 * w00, ds1 * w01);
        *(uint32_t*)(rowp + 2 * ASTRIDE) = packh2(ds0 * w10, ds1 * w11);
        *(uint32_t*)(rowp + 3 * ASTRIDE) = packh2(ds0 * w20, ds1 * w21);
    }
    __syncthreads();                   // layer-0 A visible to all pairs

    // ldmatrix base addresses (A: 32 rows per warp -> 2 m16 tiles)
    uint32_t aBase[2];
#pragma unroll
    for (int mt = 0; mt < 2; mt++) {
        int row = wm * 32 + mt * 16 + (lane & 15);
        aBase[mt] = sb + SM_A + (uint32_t)row * ASTRIDE + 16u * (lane >> 4);
    }
    // B (per-pair slab): addr = slab + (lane&15)*PSTRIDE + 16*(lane>>4)
    const uint32_t bOff = (uint32_t)(lane & 15) * PSTRIDE + 16u * (lane >> 4);

    const uint32_t vsrc  = (lane & 0x10) | (lane & 3);   // value-row lane in quad
    const bool     isval = (lane & 0xC) == 0;

    int c = 0;
    for (int L = 0; L < 4; L++) {
        float acc[2][8][4];
#pragma unroll
        for (int mt = 0; mt < 2; mt++)
#pragma unroll
            for (int nt = 0; nt < 8; nt++)
#pragma unroll
                for (int j = 0; j < 4; j++) acc[mt][nt][j] = 0.f;

        for (int kc = 0; kc < 4; kc++, c++) {       // 64-k chunks
            // first sub-chunk's A fragments: load BEFORE the wait so LDS
            // latency overlaps the B-slab arrival + barrier.
            const uint32_t k0b = (uint32_t)kc * 128;     // 64 k = 128 bytes
            uint32_t a[2][2][4];                          // [k16][mt][4]
            ldsm_x4(a[0][0], aBase[0] + k0b);
            ldsm_x4(a[0][1], aBase[1] + k0b);
            ldsm_x4(a[1][0], aBase[0] + k0b + 32);
            ldsm_x4(a[1][1], aBase[1] + k0b + 32);

            cp_wait_all();
            bar_pair(pair + 1);           // pair's slab ready, prior reads done

            if (c + 1 < 16) {             // prefetch this pair's next slab
                const char* src = (const char*)g_wp
                    + ((size_t)(c + 1) * 4 + pair) * SLAB_BYTES;
                const uint32_t dst = sb + SM_WP
                    + (uint32_t)(pair * 2 + ((c + 1) & 1)) * SLAB_BYTES;
                for (int i = wp_tid; i < SLAB_BYTES / 16; i += 64)
                    cp_async16(dst + (uint32_t)i * 16, src + (size_t)i * 16);
                cp_commit();
            }

            const uint32_t bk = sb + SM_WP
                + (uint32_t)(pair * 2 + (c & 1)) * SLAB_BYTES + bOff;

#pragma unroll
            for (int ks2 = 0; ks2 < 2; ks2++) {     // two 32-k sub-chunks
                if (ks2 == 1) {                      // second sub-chunk A
                    ldsm_x4(a[0][0], aBase[0] + k0b + 64);
                    ldsm_x4(a[0][1], aBase[1] + k0b + 64);
                    ldsm_x4(a[1][0], aBase[0] + k0b + 96);
                    ldsm_x4(a[1][1], aBase[1] + k0b + 96);
                }
#pragma unroll
                for (int k16 = 0; k16 < 2; k16++) {
                    uint32_t b[4][4];
                    const uint32_t bka = bk
                        + (uint32_t)(ks2 * 2 + k16) * (16 * PSTRIDE);
                    ldsm_x4t(b[0], bka);
                    ldsm_x4t(b[1], bka + 32);
                    ldsm_x4t(b[2], bka + 64);
                    ldsm_x4t(b[3], bka + 96);
#pragma unroll
                    for (int q = 0; q < 4; q++) {
#pragma unroll
                        for (int mt = 0; mt < 2; mt++) {
                            mma_f16(acc[mt][q * 2],     a[k16][mt], b[q]);
                            mma_f16(acc[mt][q * 2 + 1], a[k16][mt], b[q] + 2);
                        }
                    }
                }
            }
        }
        __syncthreads();   // all pairs done reading this layer's A

        if (L < 3) {
            // ---- mid-layer epilogue: silu + tangent scaling -> A fp16 ----
            const float* bias = b_hid + L * 256;
#pragma unroll
            for (int mt = 0; mt < 2; mt++) {
                int rlo = wm * 32 + mt * 16 + (lane >> 2);
#pragma unroll
                for (int nt8 = 0; nt8 < 8; nt8++) {
                    int cc = pair * 64 + nt8 * 8 + (lane & 3) * 2;
                    float2 bv = *(const float2*)(bias + cc);
                    float* a4 = acc[mt][nt8];
                    float s0 = __shfl_sync(0xffffffffu, a4[0], vsrc);
                    float s1 = __shfl_sync(0xffffffffu, a4[1], vsrc);
                    float s2 = __shfl_sync(0xffffffffu, a4[2], vsrc);
                    float s3 = __shfl_sync(0xffffffffu, a4[3], vsrc);
                    float o[4];
                    const float bb[4] = {bv.x, bv.y, bv.x, bv.y};
                    const float ss[4] = {s0, s1, s2, s3};
#pragma unroll
                    for (int j = 0; j < 4; j++) {
                        float pre = ss[j] + bb[j];
                        float sig = 1.f / (1.f + __expf(-pre));
                        if (isval) o[j] = pre * sig;
                        else {
                            float ds = sig * (1.f + pre * (1.f - sig));
                            o[j] = ds * a4[j];
                        }
                    }
                    *(uint32_t*)(smem + SM_A + rlo * ASTRIDE + cc * 2)
                        = packh2(o[0], o[1]);
                    *(uint32_t*)(smem + SM_A + (rlo + 8) * ASTRIDE + cc * 2)
                        = packh2(o[2], o[3]);
                }
            }
            __syncthreads();
        } else {
            // ---- final layer: dump fp32 C to smem (aliases A+slab region) ----
            float* C = (float*)smem;
#pragma unroll
            for (int mt = 0; mt < 2; mt++) {
                int rlo = wm * 32 + mt * 16 + (lane >> 2);
#pragma unroll
                for (int nt8 = 0; nt8 < 8; nt8++) {
                    int cc = pair * 64 + nt8 * 8 + (lane & 3) * 2;
                    float* a4 = acc[mt][nt8];
                    *(float2*)(C + rlo * CSTRIDE_F + cc)       = make_float2(a4[0], a4[1]);
                    *(float2*)(C + (rlo + 8) * CSTRIDE_F + cc) = make_float2(a4[2], a4[3]);
                }
            }
            __syncthreads();
        }
    }

    // ---- final epilogue phase 1: ALL 8 warps build softmax-state partials.
    // warp w: rows (w&1)*32+lane, cb blocks [ (w>>1)*2, +2 ).
    // Per-lane state (m, v0..v3): rt==0 lanes hold (E,P0,P1,P2),
    // rt>0 lanes hold (Q,R0,R1,R2); the quad shares m, so merging is uniform.
    {
        const float* C = (const float*)smem;
        const int row  = (wid & 1) * 32 + lane;
        const int cbg  = wid >> 1;          // 0..3
        const int rt   = lane & 3;
        const int base = lane & ~3;
        const float* Crow = C + row * CSTRIDE_F;

        float m = -1e30f, v0 = 0.f, v1 = 0.f, v2 = 0.f, v3 = 0.f;
#pragma unroll
        for (int cb = cbg * 2; cb < cbg * 2 + 2; cb++) {
            float4 q4[8];
#pragma unroll
            for (int mm = 0; mm < 8; mm++)
                q4[mm] = *(const float4*)(Crow + cb * 32 + mm * 4);
            float lg[8];
            float cmax = -1e30f;
#pragma unroll
            for (int mm = 0; mm < 8; mm++) {
                lg[mm] = __shfl_sync(0xffffffffu, q4[mm].x, base)
                         + __ldg(b_out + cb * 32 + mm * 4);
                cmax = fmaxf(cmax, lg[mm]);
            }
            float nM = fmaxf(m, cmax);
            float sc = __expf(m - nM);
            v0 *= sc; v1 *= sc; v2 *= sc; v3 *= sc;
            m = nM;
#pragma unroll
            for (int mm = 0; mm < 8; mm++) {
                float e = __expf(lg[mm] - m);
                int c0 = cb * 32 + mm * 4;
                float4 bo = *(const float4*)(b_out + c0);
                float vv0 = __shfl_sync(0xffffffffu, q4[mm].y, base) + bo.y;
                float vv1 = __shfl_sync(0xffffffffu, q4[mm].z, base) + bo.z;
                float vv2 = __shfl_sync(0xffffffffu, q4[mm].w, base) + bo.w;
                if (rt == 0) {
                    v0 += e; v1 += e * vv0; v2 += e * vv1; v3 += e * vv2;
                } else {
                    float gl = q4[mm].x;
                    v0 += e * gl;
                    v1 += e * (gl * vv0 + q4[mm].y);
                    v2 += e * (gl * vv1 + q4[mm].z);
                    v3 += e * (gl * vv2 + q4[mm].w);
                }
            }
        }
        float* P = (float*)(smem + SM_PART) + (cbg * 64 + row) * 5;
        P[0] = m; P[1] = v0; P[2] = v1; P[3] = v2; P[4] = v3;
    }
    __syncthreads();

    // ---- phase 2: warps 0-1 merge the 4 partials per lane and finish ----
    if (wid < 2) {
        const int row  = wid * 32 + lane;
        const int rt   = lane & 3;
        const int base = lane & ~3;

        float m = -1e30f, v0 = 0.f, v1 = 0.f, v2 = 0.f, v3 = 0.f;
#pragma unroll
        for (int g = 0; g < 4; g++) {
            const float* P = (const float*)(smem + SM_PART) + (g * 64 + row) * 5;
            float mg = P[0];
            float nM = fmaxf(m, mg);
            float sa = __expf(m - nM), sg = __expf(mg - nM);
            v0 = v0 * sa + P[1] * sg;
            v1 = v1 * sa + P[2] * sg;
            v2 = v2 * sa + P[3] * sg;
            v3 = v3 * sa + P[4] * sg;
            m = nM;
        }
        // rt==0: (E,P0,P1,P2) = v0..v3 ; rt>0: (Q,R0,R1,R2) = v0..v3
        float Ev = __shfl_sync(0xffffffffu, v0, base);
        float p0 = __shfl_sync(0xffffffffu, v1, base);
        float p1 = __shfl_sync(0xffffffffu, v2, base);
        float p2 = __shfl_sync(0xffffffffu, v3, base);
        float inv = 1.f / Ev;
        float t0 = p0 * inv, t1 = p1 * inv, t2 = p2 * inv;
        float S  = v0 * inv;                 // Q/E (valid on rt>0 lanes)
        float dt0 = v1 * inv - S * t0;
        float dt1 = v2 * inv - S * t1;
        float dt2 = v3 * inv - S * t2;
        // dtri[t][k] lives on lane base+1+k as dt{t}
        float d01 = __shfl_sync(0xffffffffu, dt0, base + 2);
        float d12 = __shfl_sync(0xffffffffu, dt1, base + 3);
        float d00 = __shfl_sync(0xffffffffu, dt0, base + 1);
        float d22 = __shfl_sync(0xffffffffu, dt2, base + 3);
        float d10 = __shfl_sync(0xffffffffu, dt1, base + 1);
        float d21 = __shfl_sync(0xffffffffu, dt2, base + 2);
        if (rt == 0) {
            int samp = blockIdx.x * 16 + (row >> 2);
            out[samp * 3 + 0] =  d01 + d12;
            out[samp * 3 + 1] = -d00 + d22;
            out[samp * 3 + 2] = -d10 - d21;
        }
    }
}

// ---------------------------------------------------------------------------
extern "C" void kernel_launch(void* const* d_in, const int* in_sizes, int n_in,
                              void* d_out, int out_size)
{
    const float* x     = (const float*)d_in[0];
    const float* w_in  = (const float*)d_in[1];
    const float* b_in  = (const float*)d_in[2];
    const float* w_hid = (const float*)d_in[3];
    const float* b_hid = (const float*)d_in[4];
    const float* w_out = (const float*)d_in[5];
    const float* b_out = (const float*)d_in[6];
    float*       out   = (float*)d_out;

    const int N = in_sizes[0] / 3;   // 65536 samples

    prep_kernel<<<1024, 256>>>(w_hid, w_out);

    cudaFuncSetAttribute(divfree_main,
                         cudaFuncAttributeMaxDynamicSharedMemorySize, SMEM_TOTAL);
    divfree_main<<<N / 16, THREADS, SMEM_TOTAL>>>(x, w_in, b_in, b_hid, b_out, out);
    (void)n_in; (void)out_size;
}